// round 9
// baseline (speedup 1.0000x reference)
#include <cuda_runtime.h>

// out[b, H-1-h, w] = exp(EPS)*o[0] + sum_{d=1}^{D-1} (prod_{k<d}(1-o[k])) * o[d]
// o = clip(v, EPS, 1-EPS).
//
// Two-kernel depth-split scan:
//   Kernel 1 (unchanged from R7 win): NSEG=8 segments of 16 slices. One CTA =
//     256 consecutive float4-rays of one segment -> every depth step is a 4KB
//     fully-contiguous CTA read. Partial pairs (A_s, T_s) to __device__ scratch.
//   Kernel 2 (new): batched fold. All 8 A-parts + 7 T-parts loaded into
//     registers up-front (15 independent LDG.128, one L2 round trip), then the
//     combine chain runs on registers. 512 CTAs x 128 threads.

#define EPSF      1e-5f
#define ONE_MEPS  (1.0f - 1e-5f)
#define EXP_EPS   1.0000100000500002f   // expf(1e-5f)

#define D_      128
#define H_      128
#define W4_     32
#define NRAY    65536                   // B*H*W4 float4-rays
#define NSEG    8
#define SEGD    (D_ / NSEG)             // 16
#define SLICE4  (H_ * W4_)              // float4 per depth slice (4096)

__device__ float4 g_Apart[NSEG * NRAY];   // 8 MB
__device__ float4 g_Tpart[NSEG * NRAY];   // 8 MB

static __device__ __forceinline__ float clipv(float v) {
    return fminf(fmaxf(v, EPSF), ONE_MEPS);
}

__global__ void __launch_bounds__(256)
seg_scan_kernel(const float* __restrict__ vox) {
    // blockIdx: low 8 bits = ray group (256 groups of 256 rays), high bits = segment
    int group = blockIdx.x & 255;
    int seg   = blockIdx.x >> 8;
    int ray   = group * 256 + threadIdx.x;      // consecutive across the CTA

    int inSlice = ray & (SLICE4 - 1);           // (h, w4) packed, contiguous
    int b       = ray >> 12;                    // 4096 float4-rays per batch

    const float4* p = reinterpret_cast<const float4*>(vox)
                    + (size_t)b * D_ * SLICE4
                    + (size_t)(seg * SEGD) * SLICE4
                    + inSlice;

    // first slice of segment: weight exp(EPS) only for the global d=0 term
    float w0 = (seg == 0) ? EXP_EPS : 1.0f;
    float4 v0 = p[0];
    float ox = clipv(v0.x), oy = clipv(v0.y), oz = clipv(v0.z), ow = clipv(v0.w);
    float ax = w0 * ox, ay = w0 * oy, az = w0 * oz, aw = w0 * ow;
    float Tx = 1.0f, Ty = 1.0f, Tz = 1.0f, Tw = 1.0f;

    #pragma unroll 5
    for (int d = 1; d < SEGD; ++d) {
        float4 c = p[(size_t)d * SLICE4];
        float cx = clipv(c.x), cy = clipv(c.y), cz = clipv(c.z), cw = clipv(c.w);
        Tx *= (1.0f - ox);  Ty *= (1.0f - oy);
        Tz *= (1.0f - oz);  Tw *= (1.0f - ow);
        ax = fmaf(Tx, cx, ax);  ay = fmaf(Ty, cy, ay);
        az = fmaf(Tz, cz, az);  aw = fmaf(Tw, cw, aw);
        ox = cx; oy = cy; oz = cz; ow = cw;
    }
    // close the segment transmittance: include last element
    Tx *= (1.0f - ox);  Ty *= (1.0f - oy);
    Tz *= (1.0f - oz);  Tw *= (1.0f - ow);

    g_Apart[seg * NRAY + ray] = make_float4(ax, ay, az, aw);
    g_Tpart[seg * NRAY + ray] = make_float4(Tx, Ty, Tz, Tw);
}

__global__ void __launch_bounds__(128)
seg_fold_kernel(float* __restrict__ out) {
    int ray = blockIdx.x * blockDim.x + threadIdx.x;   // 65536

    // Batch ALL scratch loads before any combine arithmetic: 15 independent
    // LDG.128 in flight -> one (L2) round trip instead of a serial chain.
    float4 A[NSEG];
    float4 T[NSEG - 1];
    #pragma unroll
    for (int s = 0; s < NSEG; ++s)
        A[s] = g_Apart[s * NRAY + ray];
    #pragma unroll
    for (int s = 0; s < NSEG - 1; ++s)
        T[s] = g_Tpart[s * NRAY + ray];

    float4 acc = A[0];
    float4 Tr  = T[0];
    #pragma unroll
    for (int s = 1; s < NSEG; ++s) {
        acc.x = fmaf(Tr.x, A[s].x, acc.x);  acc.y = fmaf(Tr.y, A[s].y, acc.y);
        acc.z = fmaf(Tr.z, A[s].z, acc.z);  acc.w = fmaf(Tr.w, A[s].w, acc.w);
        if (s < NSEG - 1) {
            Tr.x *= T[s].x;  Tr.y *= T[s].y;  Tr.z *= T[s].z;  Tr.w *= T[s].w;
        }
    }

    int w4 = ray & (W4_ - 1);
    int h  = (ray >> 5) & (H_ - 1);
    int b  = ray >> 12;                        // 4096 float4-rays per batch

    reinterpret_cast<float4*>(out)[(size_t)b * H_ * W4_
                                   + (size_t)(H_ - 1 - h) * W4_ + w4] = acc;
}

extern "C" void kernel_launch(void* const* d_in, const int* in_sizes, int n_in,
                              void* d_out, int out_size) {
    const float* vox = (const float*)d_in[0];
    float* out = (float*)d_out;
    seg_scan_kernel<<<256 * NSEG, 256>>>(vox);    // 2048 CTAs
    seg_fold_kernel<<<NRAY / 128, 128>>>(out);    // 512 CTAs
}

// round 10
// speedup vs baseline: 3.5993x; 3.5993x over previous
#include <cuda_runtime.h>

// out[b, H-1-h, w] = exp(EPS)*o[0] + sum_{d=1}^{D-1} (prod_{k<d}(1-o[k])) * o[d]
// o = clip(v, EPS, 1-EPS).
//
// Monolithic scalar-per-thread scan with EARLY RAY TERMINATION (exact):
// once every lane in the warp has transmittance T < TCUT, the neglected tail
// sum is <= T < TCUT (the remaining termination-prob mass of a ray is bounded
// by its current transmittance), while out >= exp(EPS)*clip(v0) >= 1e-5,
// so rel err <= TCUT/1e-5 = 1e-5 worst case. The check uses actual values,
// so correctness is input-independent; only speed is input-adaptive.
//
// Layout: 262144 threads, one float-column (ray) each; a warp covers 32
// consecutive w -> one contiguous 128B line per depth slice. Depth walked in
// chunks of 8 with all 8 loads batched (MLP=8), warp vote per chunk.

#define EPSF       1e-5f
#define ONE_MEPS   (1.0f - 1e-5f)
#define EXP_EPS_M1 1.00000500002e-5f    // expf(1e-5f) - 1
#define TCUT       1e-10f

#define D_     128
#define H_     128
#define W_     128
#define SLICE  (H_ * W_)                // floats per depth slice (16384)

static __device__ __forceinline__ float clipv(float v) {
    return fminf(fmaxf(v, EPSF), ONE_MEPS);
}

__global__ void __launch_bounds__(256)
eff_loss_kernel(const float* __restrict__ vox, float* __restrict__ out) {
    int tid = blockIdx.x * blockDim.x + threadIdx.x;   // 262144 rays
    int w = tid & (W_ - 1);
    int h = (tid >> 7) & (H_ - 1);
    int b =  tid >> 14;

    const float* p = vox + (size_t)b * D_ * SLICE + (size_t)h * W_ + w;

    float a = 0.0f, T = 1.0f, o0 = 0.0f;

    for (int base = 0; base < D_; base += 8) {
        // batch the 8 independent loads of this chunk
        float v[8];
        #pragma unroll
        for (int j = 0; j < 8; ++j)
            v[j] = p[(size_t)(base + j) * SLICE];

        #pragma unroll
        for (int j = 0; j < 8; ++j) {
            float o = clipv(v[j]);
            if (base == 0 && j == 0) o0 = o;
            a = fmaf(T, o, a);        // accumulate termination prob
            T = fmaf(-o, T, T);       // T *= (1 - o)
        }

        // early ray termination: tail mass <= T for every lane
        if (__all_sync(0xffffffffu, T < TCUT)) break;
    }

    // d=0 term carries weight exp(EPS) instead of 1
    a = fmaf(EXP_EPS_M1, o0, a);

    // vertical flip on h
    out[(size_t)b * SLICE + (size_t)(H_ - 1 - h) * W_ + w] = a;
}

extern "C" void kernel_launch(void* const* d_in, const int* in_sizes, int n_in,
                              void* d_out, int out_size) {
    const float* vox = (const float*)d_in[0];
    float* out = (float*)d_out;
    constexpr int TOTAL = 16 * H_ * W_;     // 262144 threads
    eff_loss_kernel<<<TOTAL / 256, 256>>>(vox, out);
}